// round 12
// baseline (speedup 1.0000x reference)
#include <cuda_runtime.h>
#include <cuda_bf16.h>

// out[t, :] = W[x[t], :] + b    t in [0, 8192), D = 2048
//
// Best so far: persistent pipelined gather (R9, 18.53us). This deepens it:
// 2 tokens per iteration -> 4 independent row-float4 loads in flight per
// thread in steady state, 2-ahead index prefetch (one int2 per iter), half
// the loop/branch overhead. Loads issue while previous tokens are being
// summed/stored, so the load duty cycle stays ~100%. Stores evict-first.
// TOKENS % (2*GRID) == 0 (8192 = 2368*3 + ... no—) GRID=1024: 8192/(2*1024)=4 iters exactly.

#define D_MODEL 2048
#define D4      (D_MODEL / 4)   // 512 float4 per row
#define TOKENS  8192
#define GRID    1024            // 8192 tokens = 4 iterations of 2 tokens/CTA
#define NTHR    256

__global__ __launch_bounds__(NTHR)
void embed_gather_pipe2(const int2* __restrict__ x2,
                        const float4* __restrict__ W4,
                        const float4* __restrict__ b4,
                        float4* __restrict__ out4) {
    const int c0 = threadIdx.x;
    const int c1 = threadIdx.x + NTHR;

    const float4 bb0 = b4[c0];
    const float4 bb1 = b4[c1];

    // token pairs: CTA bid handles pairs {bid, bid+GRID, bid+2*GRID, bid+3*GRID}
    int p = blockIdx.x;

    // prologue: indices + row loads for pair 0, index prefetch for pair 1
    int2 rr = __ldg(x2 + p);
    int2 rr_n = __ldg(x2 + p + GRID);

    unsigned o0 = (unsigned)rr.x * D4;
    unsigned o1 = (unsigned)rr.y * D4;
    float4 a00 = W4[o0 + c0];
    float4 a01 = W4[o0 + c1];
    float4 a10 = W4[o1 + c0];
    float4 a11 = W4[o1 + c1];

#pragma unroll
    for (int it = 0; it < 4; it++) {
        const bool have_next = (it < 3);

        // prefetch indices two pairs ahead
        int2 rr_n2;
        if (it < 2) rr_n2 = __ldg(x2 + p + 2 * GRID);

        // issue next pair's row loads before consuming current
        float4 n00, n01, n10, n11;
        if (have_next) {
            const unsigned no0 = (unsigned)rr_n.x * D4;
            const unsigned no1 = (unsigned)rr_n.y * D4;
            n00 = W4[no0 + c0];
            n01 = W4[no0 + c1];
            n10 = W4[no1 + c0];
            n11 = W4[no1 + c1];
        }

        // consume current pair
        float4 v00 = a00, v01 = a01, v10 = a10, v11 = a11;
        v00.x += bb0.x; v00.y += bb0.y; v00.z += bb0.z; v00.w += bb0.w;
        v01.x += bb1.x; v01.y += bb1.y; v01.z += bb1.z; v01.w += bb1.w;
        v10.x += bb0.x; v10.y += bb0.y; v10.z += bb0.z; v10.w += bb0.w;
        v11.x += bb1.x; v11.y += bb1.y; v11.z += bb1.z; v11.w += bb1.w;

        float4* __restrict__ dst = out4 + (unsigned)p * (2 * D4);
        __stcs(dst + c0, v00);
        __stcs(dst + c1, v01);
        __stcs(dst + D4 + c0, v10);
        __stcs(dst + D4 + c1, v11);

        if (!have_next) break;
        p += GRID;
        rr_n = rr_n2;
        a00 = n00; a01 = n01; a10 = n10; a11 = n11;
    }
}

extern "C" void kernel_launch(void* const* d_in, const int* in_sizes, int n_in,
                              void* d_out, int out_size) {
    const int2*   x = (const int2*)d_in[0];       // [8192] int32 as 4096 pairs
    const float4* W = (const float4*)d_in[1];     // [50257, 2048] f32
    const float4* b = (const float4*)d_in[2];     // [2048] f32
    float4* out = (float4*)d_out;                 // [4, 2048, 2048] f32

    embed_gather_pipe2<<<GRID, NTHR>>>(x, W, b, out);
}

// round 13
// speedup vs baseline: 1.0718x; 1.0718x over previous
#include <cuda_runtime.h>
#include <cuda_bf16.h>

// out[t, :] = W[x[t], :] + b    t in [0, 8192), D = 2048
//
// Refinement of the best kernel (R9, 18.53us): persistent depth-1 pipelined
// gather, GRID = 1184 = 8 CTAs/SM x 148 SMs (exactly resident, occ ~93%).
// R12 lesson: chip-wide loads-in-flight = resident warps x per-warp MLP;
// losing occupancy to deepen the pipeline is a net loss. Changes here:
//  - __launch_bounds__(256,8): pin regs<=32 so 8 CTAs/SM is guaranteed
//  - first 6 iterations are unconditionally full (8192 = 1184*6 + 1088):
//    branch-light main loop, predicated tail only at the end
//  - 32-bit unsigned offsets; evict-first stores; 2-ahead index prefetch

#define D_MODEL 2048
#define D4      (D_MODEL / 4)   // 512 float4 per row
#define TOKENS  8192
#define GRID    1184            // 8 CTAs/SM * 148 SMs, all resident
#define NTHR    256
#define FULL_ITERS 6            // every CTA has at least 7 tokens? 8192/1184=6.92
                                // tokens t = bid + k*GRID valid for k<=6 iff bid<1088;
                                // k in [0,5] valid for ALL bids (bid+5*GRID<=7103<8192)

__global__ __launch_bounds__(NTHR, 8)
void embed_gather_pipe(const int* __restrict__ x,
                       const float4* __restrict__ W4,
                       const float4* __restrict__ b4,
                       float4* __restrict__ out4) {
    const int c0 = threadIdx.x;
    const int c1 = threadIdx.x + NTHR;

    const float4 bb0 = b4[c0];
    const float4 bb1 = b4[c1];

    int t = blockIdx.x;

    // prologue: current row loads + next index (t+GRID always < TOKENS since
    // blockIdx.x + 1184 <= 2367 < 8192)
    unsigned o = (unsigned)__ldg(x + t) * D4;
    unsigned r_nxt = (unsigned)__ldg(x + t + GRID);

    float4 a0 = W4[o + c0];
    float4 a1 = W4[o + c1];

    // ---- main loop: iterations 0..FULL_ITERS-1, next token always exists ----
#pragma unroll
    for (int it = 0; it < FULL_ITERS; it++) {
        const int t2 = t + 2 * GRID;
        // index two ahead (may be OOB only when it==FULL_ITERS-1 for large bid)
        unsigned r_nxt2 = 0;
        if (t2 < TOKENS) r_nxt2 = (unsigned)__ldg(x + t2);

        // issue next row's loads before consuming current
        const unsigned no = r_nxt * D4;
        float4 n0 = W4[no + c0];
        float4 n1 = W4[no + c1];

        float4 v0 = a0, v1 = a1;
        v0.x += bb0.x; v0.y += bb0.y; v0.z += bb0.z; v0.w += bb0.w;
        v1.x += bb1.x; v1.y += bb1.y; v1.z += bb1.z; v1.w += bb1.w;

        float4* __restrict__ dst = out4 + (unsigned)t * D4;
        __stcs(dst + c0, v0);
        __stcs(dst + c1, v1);

        t += GRID;
        r_nxt = r_nxt2;
        a0 = n0; a1 = n1;
    }

    // ---- iteration 6: always valid token (t = bid + 6*GRID <= 9470? no:
    // bid+6*1184 = bid+7104 < 8192 iff bid < 1088). a0/a1 hold its row only
    // if the loop's last prefetch was valid, which it was iff t < TOKENS. ----
    if (t < TOKENS) {
        float4 v0 = a0, v1 = a1;
        v0.x += bb0.x; v0.y += bb0.y; v0.z += bb0.z; v0.w += bb0.w;
        v1.x += bb1.x; v1.y += bb1.y; v1.z += bb1.z; v1.w += bb1.w;
        float4* __restrict__ dst = out4 + (unsigned)t * D4;
        __stcs(dst + c0, v0);
        __stcs(dst + c1, v1);
    }
}

extern "C" void kernel_launch(void* const* d_in, const int* in_sizes, int n_in,
                              void* d_out, int out_size) {
    const int*    x = (const int*)d_in[0];        // [4, 2048] int32
    const float4* W = (const float4*)d_in[1];     // [50257, 2048] f32
    const float4* b = (const float4*)d_in[2];     // [2048] f32
    float4* out = (float4*)d_out;                 // [4, 2048, 2048] f32

    embed_gather_pipe<<<GRID, NTHR>>>(x, W, b, out);
}